// round 16
// baseline (speedup 1.0000x reference)
#include <cuda_runtime.h>
#include <cuda_fp16.h>
#include <cstdint>
#include <math.h>

// ---------------------------------------------------------------------------
// Round 16: R15 (741us best) with ALL grid barriers replaced by counter
// dataflow. Pool waits on its own rowblocks; mlp on poolc; route on mlpc;
// next segment's tiles on ready>=16 (gemm 8 + route 8). Route overlaps the
// next segment's GEMM. GEMM inner loop unchanged.
// ---------------------------------------------------------------------------

#define M_TOT   6272
#define CDIM    512
#define HW      196
#define BATCH   32
#define HIDN    128
#define AANCH   3
#define NELEM   (M_TOT * CDIM)
#define NLAYER  18

#define BM 128
#define BN 64
#define BK 64
#define KSTAGES 8
#define SA_HI 0
#define SA_LO 16384
#define SB_HI 32768
#define SB_LO 40960
#define STAGE_BYTES 49152
#define SMEM_DYN (1024 + 2 * STAGE_BYTES)

#define NCTA 296
#define NTILE 392
#define NRB  49

__device__ float g_bufA[NELEM];
__device__ float g_anc0[NELEM];
__device__ float g_anc1[NELEM];
__device__ float g_anc2[NELEM];
__device__ float g_gates[BATCH * AANCH * CDIM];
__device__ float g_pp[3 * BATCH * CDIM];
__device__ float g_f1wT[AANCH * HIDN * CDIM];
__device__ float g_f2wT[AANCH * AANCH * CDIM * HIDN];
__device__ __half g_Ahi[2 * NELEM];
__device__ __half g_Alo[2 * NELEM];
__device__ __half g_Whi[NLAYER * CDIM * CDIM];   // [l][n][k]
__device__ __half g_Wlo[NLAYER * CDIM * CDIM];
__device__ int g_q[4];                            // per-segment queue heads
__device__ int g_ready[NLAYER * NRB * 8];         // padded ready counters
__device__ int g_gc[6 * 8];                       // poolc[s]=g_gc[s*16?]  (padded)

// ---------------------------------------------------------------------------
__device__ __forceinline__ void wait_ge(const int* p, int v) {
    if (threadIdx.x == 0) {
        while (__ldcg(p) < v) __nanosleep(64);
        __threadfence();
    }
    __syncthreads();
}
__device__ __forceinline__ void signal1(int* p, int v) {
    __syncthreads();
    if (threadIdx.x == 0) {
        __threadfence();
        atomicAdd(p, v);
    }
}
__device__ __forceinline__ uint32_t sw128(uint32_t off) {
    return off ^ ((off >> 3) & 0x70);
}
__device__ __forceinline__ void cpa16(uint32_t s, const void* g) {
    asm volatile("cp.async.cg.shared.global [%0], [%1], 16;" :: "r"(s), "l"(g));
}
__device__ __forceinline__ void cpa_commit() {
    asm volatile("cp.async.commit_group;" ::: "memory");
}
__device__ __forceinline__ void cpa_wait1() {
    asm volatile("cp.async.wait_group 1;" ::: "memory");
}
__device__ __forceinline__ void ldsm_x4(uint32_t& r0, uint32_t& r1, uint32_t& r2,
                                        uint32_t& r3, uint32_t a) {
    asm volatile("ldmatrix.sync.aligned.m8n8.x4.shared.b16 {%0,%1,%2,%3}, [%4];"
                 : "=r"(r0), "=r"(r1), "=r"(r2), "=r"(r3) : "r"(a));
}
__device__ __forceinline__ void mma_f16(float* c, const uint32_t* a, const uint32_t* b) {
    asm volatile(
        "mma.sync.aligned.m16n8k16.row.col.f32.f16.f16.f32 "
        "{%0,%1,%2,%3},{%4,%5,%6,%7},{%8,%9},{%0,%1,%2,%3};"
        : "+f"(c[0]), "+f"(c[1]), "+f"(c[2]), "+f"(c[3])
        : "r"(a[0]), "r"(a[1]), "r"(a[2]), "r"(a[3]), "r"(b[0]), "r"(b[1]));
}
__device__ __forceinline__ float gelu_fast(float x) {
    float u = 0.7978845608028654f * fmaf(0.044715f * x, x * x, x);
    float e = __expf(2.0f * u);
    return 0.5f * x * (1.0f + (1.0f - 2.0f / (e + 1.0f)));
}
__device__ __forceinline__ float gelu_tanh(float x) {
    float x3 = x * x * x;
    return 0.5f * x * (1.0f + tanhf(0.7978845608028654f * (x + 0.044715f * x3)));
}
__device__ __forceinline__ uint32_t pack_h2(float a, float b) {
    __half2 t = __floats2half2_rn(a, b);
    return *reinterpret_cast<uint32_t*>(&t);
}
__device__ __forceinline__ __half2 split_hi2(float a, float b, float& la, float& lb) {
    __half ha = __float2half_rn(a);
    __half hb = __float2half_rn(b);
    la = a - __half2float(ha);
    lb = b - __half2float(hb);
    __half2 h; h.x = ha; h.y = hb;
    return h;
}

// ---------------------------------------------------------------------------
// One 128x64 output tile (R6/R8/R12-proven inner structure — UNCHANGED).
// ---------------------------------------------------------------------------
__device__ void gemm_tile(uint32_t sb, int bm, int bn,
                          const __half* __restrict__ aHi, const __half* __restrict__ aLo,
                          const __half* __restrict__ bHi, const __half* __restrict__ bLo,
                          const float* __restrict__ bias,
                          float* __restrict__ out,
                          __half* __restrict__ nHi, __half* __restrict__ nLo) {
    const int t = threadIdx.x;
    const int lane = t & 31;
    const int w = t >> 5;
    const int wm = (w >> 1) * 32;
    const int wn = (w & 1) * 32;

    const int a_row = t >> 3;
    const int a_c16 = t & 7;

    auto load_stage = [&](int s, int buf) {
        const int k0 = s * BK;
        const uint32_t stg = sb + (uint32_t)buf * STAGE_BYTES;
#pragma unroll
        for (int p = 0; p < 4; ++p) {
            const int row = p * 32 + a_row;
            const uint32_t so = sw128((uint32_t)row * 128 + a_c16 * 16);
            const size_t gofs = (size_t)(bm + row) * CDIM + k0 + a_c16 * 8;
            cpa16(stg + SA_HI + so, aHi + gofs);
            cpa16(stg + SA_LO + so, aLo + gofs);
        }
#pragma unroll
        for (int p = 0; p < 2; ++p) {
            const int row = p * 32 + a_row;
            const uint32_t so = sw128((uint32_t)row * 128 + a_c16 * 16);
            const size_t gofs = (size_t)(bn + row) * CDIM + k0 + a_c16 * 8;
            cpa16(stg + SB_HI + so, bHi + gofs);
            cpa16(stg + SB_LO + so, bLo + gofs);
        }
    };

    uint32_t a_off[2];
#pragma unroll
    for (int mi = 0; mi < 2; ++mi)
        a_off[mi] = (uint32_t)(wm + mi * 16 + (lane & 15)) * 128 + ((lane >> 4) & 1) * 16;
    uint32_t b_off[2];
#pragma unroll
    for (int g = 0; g < 2; ++g)
        b_off[g] = (uint32_t)(wn + g * 16 + ((lane >> 4) & 1) * 8 + (lane & 7)) * 128 +
                   ((lane >> 3) & 1) * 16;

    float acc[2][4][4];
#pragma unroll
    for (int mi = 0; mi < 2; ++mi)
#pragma unroll
        for (int nf = 0; nf < 4; ++nf)
#pragma unroll
            for (int r = 0; r < 4; ++r) acc[mi][nf][r] = 0.0f;

    load_stage(0, 0); cpa_commit();
    load_stage(1, 1); cpa_commit();

    uint32_t ah[2][4], bh[2][4], ahn[2][4], bhn[2][4], al[2][4], bl[2][4];

#pragma unroll 1
    for (int s = 0; s < KSTAGES; ++s) {
        cpa_wait1();
        __syncthreads();
        const int buf = s & 1;
        const uint32_t stg = sb + (uint32_t)buf * STAGE_BYTES;

#pragma unroll
        for (int mi = 0; mi < 2; ++mi)
            ldsm_x4(ah[mi][0], ah[mi][1], ah[mi][2], ah[mi][3],
                    stg + SA_HI + sw128(a_off[mi]));
#pragma unroll
        for (int g = 0; g < 2; ++g)
            ldsm_x4(bh[g][0], bh[g][1], bh[g][2], bh[g][3],
                    stg + SB_HI + sw128(b_off[g]));

#pragma unroll
        for (int kk = 0; kk < 4; ++kk) {
            const uint32_t kb = kk * 32;
#pragma unroll
            for (int mi = 0; mi < 2; ++mi)
                ldsm_x4(al[mi][0], al[mi][1], al[mi][2], al[mi][3],
                        stg + SA_LO + sw128(a_off[mi] + kb));
#pragma unroll
            for (int g = 0; g < 2; ++g)
                ldsm_x4(bl[g][0], bl[g][1], bl[g][2], bl[g][3],
                        stg + SB_LO + sw128(b_off[g] + kb));
            if (kk < 3) {
                const uint32_t kbn = kb + 32;
#pragma unroll
                for (int mi = 0; mi < 2; ++mi)
                    ldsm_x4(ahn[mi][0], ahn[mi][1], ahn[mi][2], ahn[mi][3],
                            stg + SA_HI + sw128(a_off[mi] + kbn));
#pragma unroll
                for (int g = 0; g < 2; ++g)
                    ldsm_x4(bhn[g][0], bhn[g][1], bhn[g][2], bhn[g][3],
                            stg + SB_HI + sw128(b_off[g] + kbn));
            }
#pragma unroll
            for (int mi = 0; mi < 2; ++mi)
#pragma unroll
                for (int nf = 0; nf < 4; ++nf)
                    mma_f16(acc[mi][nf], ah[mi], &bh[nf >> 1][(nf & 1) * 2]);
#pragma unroll
            for (int mi = 0; mi < 2; ++mi)
#pragma unroll
                for (int nf = 0; nf < 4; ++nf)
                    mma_f16(acc[mi][nf], al[mi], &bh[nf >> 1][(nf & 1) * 2]);
#pragma unroll
            for (int mi = 0; mi < 2; ++mi)
#pragma unroll
                for (int nf = 0; nf < 4; ++nf)
                    mma_f16(acc[mi][nf], ah[mi], &bl[nf >> 1][(nf & 1) * 2]);
            if (kk < 3) {
#pragma unroll
                for (int mi = 0; mi < 2; ++mi)
#pragma unroll
                    for (int r = 0; r < 4; ++r) ah[mi][r] = ahn[mi][r];
#pragma unroll
                for (int g = 0; g < 2; ++g)
#pragma unroll
                    for (int r = 0; r < 4; ++r) bh[g][r] = bhn[g][r];
            }
        }
        __syncthreads();
        if (s + 2 < KSTAGES) load_stage(s + 2, buf);
        cpa_commit();
    }

    const int r0 = bm + wm + (lane >> 2);
    const int cbase = bn + wn + (lane & 3) * 2;
#pragma unroll
    for (int mi = 0; mi < 2; ++mi) {
#pragma unroll
        for (int nf = 0; nf < 4; ++nf) {
            const int c = cbase + nf * 8;
            const float2 bv = *reinterpret_cast<const float2*>(&bias[c]);
            const int ra = r0 + mi * 16;
            const int rb = ra + 8;
            float v0 = gelu_fast(acc[mi][nf][0] + bv.x);
            float v1 = gelu_fast(acc[mi][nf][1] + bv.y);
            float v2 = gelu_fast(acc[mi][nf][2] + bv.x);
            float v3 = gelu_fast(acc[mi][nf][3] + bv.y);
            if (out) {
                *reinterpret_cast<float2*>(&out[(size_t)ra * CDIM + c]) = make_float2(v0, v1);
                *reinterpret_cast<float2*>(&out[(size_t)rb * CDIM + c]) = make_float2(v2, v3);
            }
            if (nHi) {
                float l0, l1, l2, l3;
                __half2 h01 = split_hi2(v0, v1, l0, l1);
                __half2 h23 = split_hi2(v2, v3, l2, l3);
                *reinterpret_cast<__half2*>(&nHi[(size_t)ra * CDIM + c]) = h01;
                *reinterpret_cast<__half2*>(&nHi[(size_t)rb * CDIM + c]) = h23;
                *reinterpret_cast<uint32_t*>(&nLo[(size_t)ra * CDIM + c]) = pack_h2(l0, l1);
                *reinterpret_cast<uint32_t*>(&nLo[(size_t)rb * CDIM + c]) = pack_h2(l2, l3);
            }
        }
    }
}

// ---------------------------------------------------------------------------
__device__ __noinline__ void pool_part(int bid, const float* __restrict__ act) {
    const int b = bid / 3;
    const int part = bid % 3;
    const int r0 = part * 66;
    const int rcnt = (part == 2) ? 64 : 66;
    const int t = threadIdx.x;
    const int c = t * 2;

    const float* p = act + (size_t)(b * HW + r0) * CDIM + c;
    float sx = 0.f, sy = 0.f;
#pragma unroll 4
    for (int r = 0; r < rcnt; ++r) {
        float2 v = __ldcg(reinterpret_cast<const float2*>(p + (size_t)r * CDIM));
        sx += v.x; sy += v.y;
    }
    *reinterpret_cast<float2*>(&g_pp[(size_t)(part * BATCH + b) * CDIM + c]) =
        make_float2(sx, sy);
}

__device__ __noinline__ void mlp_phase(char* sm, int b,
                                       const float* __restrict__ f1wT,
                                       const float* __restrict__ f1b,
                                       const float* __restrict__ f2wT,
                                       const float* __restrict__ f2b,
                                       float* __restrict__ gates) {
    float* ps = (float*)sm;
    float* hs = ps + CDIM;
    float* lg = hs + HIDN;
    const int t = threadIdx.x;

    for (int i = t; i < CDIM; i += 256) {
        float s = __ldcg(&g_pp[(size_t)(0 * BATCH + b) * CDIM + i]) +
                  __ldcg(&g_pp[(size_t)(1 * BATCH + b) * CDIM + i]) +
                  __ldcg(&g_pp[(size_t)(2 * BATCH + b) * CDIM + i]);
        ps[i] = s * (1.0f / (float)HW);
    }
    __syncthreads();

    if (t < HIDN) {
        float acc = f1b[t];
        const float4* wr = reinterpret_cast<const float4*>(f1wT + (size_t)t * CDIM);
#pragma unroll 4
        for (int k4 = 0; k4 < CDIM / 4; ++k4) {
            float4 w = wr[k4];
            acc = fmaf(ps[k4 * 4 + 0], w.x, acc);
            acc = fmaf(ps[k4 * 4 + 1], w.y, acc);
            acc = fmaf(ps[k4 * 4 + 2], w.z, acc);
            acc = fmaf(ps[k4 * 4 + 3], w.w, acc);
        }
        hs[t] = gelu_tanh(acc);
    }
    __syncthreads();

#pragma unroll 1
    for (int j = t; j < AANCH * CDIM; j += 256) {
        float acc = f2b[j];
        const float4* wr = reinterpret_cast<const float4*>(f2wT + (size_t)j * HIDN);
#pragma unroll 8
        for (int k4 = 0; k4 < HIDN / 4; ++k4) {
            float4 w = wr[k4];
            acc = fmaf(hs[k4 * 4 + 0], w.x, acc);
            acc = fmaf(hs[k4 * 4 + 1], w.y, acc);
            acc = fmaf(hs[k4 * 4 + 2], w.z, acc);
            acc = fmaf(hs[k4 * 4 + 3], w.w, acc);
        }
        lg[j] = acc;
    }
    __syncthreads();

    for (int c = t; c < CDIM; c += 256) {
        float l0 = lg[c], l1 = lg[CDIM + c], l2 = lg[2 * CDIM + c];
        float m = fmaxf(l0, fmaxf(l1, l2));
        float e0 = expf(l0 - m), e1 = expf(l1 - m), e2 = expf(l2 - m);
        float inv = 1.0f / (e0 + e1 + e2);
        gates[b * AANCH * CDIM + c]            = e0 * inv;
        gates[b * AANCH * CDIM + CDIM + c]     = e1 * inv;
        gates[b * AANCH * CDIM + 2 * CDIM + c] = e2 * inv;
    }
}

// routed residual for one rowblock (128 rows x 512 cols)
__device__ __noinline__ void route_rb(int rb, float* __restrict__ nx,
                                      const float* __restrict__ a0,
                                      const float* __restrict__ a1,
                                      const float* __restrict__ a2,
                                      const float* __restrict__ gates, float gamma,
                                      __half* __restrict__ nhi, __half* __restrict__ nlo) {
    const int t = threadIdx.x;
#pragma unroll 1
    for (int idx = t; idx < 128 * 128; idx += 256) {
        const int row = rb * 128 + (idx >> 7);
        const int c4  = idx & 127;
        const int b   = row / HW;
        const int i   = row * 128 + c4;

        const float4 g0 = __ldcg(reinterpret_cast<const float4*>(&gates[b * AANCH * CDIM + c4 * 4]));
        const float4 g1 = __ldcg(reinterpret_cast<const float4*>(&gates[b * AANCH * CDIM + CDIM + c4 * 4]));
        const float4 g2 = __ldcg(reinterpret_cast<const float4*>(&gates[b * AANCH * CDIM + 2 * CDIM + c4 * 4]));

        float4 v  = __ldcg(reinterpret_cast<const float4*>(nx) + i);
        float4 x0 = __ldcg(reinterpret_cast<const float4*>(a0) + i);
        float4 x1 = __ldcg(reinterpret_cast<const float4*>(a1) + i);
        float4 x2 = __ldcg(reinterpret_cast<const float4*>(a2) + i);

        v.x += gamma * (g0.x * x0.x + g1.x * x1.x + g2.x * x2.x);
        v.y += gamma * (g0.y * x0.y + g1.y * x1.y + g2.y * x2.y);
        v.z += gamma * (g0.z * x0.z + g1.z * x1.z + g2.z * x2.z);
        v.w += gamma * (g0.w * x0.w + g1.w * x1.w + g2.w * x2.w);

        reinterpret_cast<float4*>(nx)[i] = v;

        if (nhi) {
            float l0, l1, l2, l3;
            __half2 h01 = split_hi2(v.x, v.y, l0, l1);
            __half2 h23 = split_hi2(v.z, v.w, l2, l3);
            reinterpret_cast<uint2*>(nhi)[i] = make_uint2(*reinterpret_cast<uint32_t*>(&h01),
                                                          *reinterpret_cast<uint32_t*>(&h23));
            reinterpret_cast<uint2*>(nlo)[i] = make_uint2(pack_h2(l0, l1), pack_h2(l2, l3));
        }
    }
}

__device__ __forceinline__ float* layer_dst(int l, float* outp) {
    if (l == 1)  return g_anc0;
    if (l == 4)  return g_anc1;
    if (l == 9)  return g_anc2;
    if (l == 17) return outp;
    if (l == 11 || l == 14) return g_bufA;
    return nullptr;
}

// ---------------------------------------------------------------------------
__global__ __launch_bounds__(256, 2)
void stage_mega(const float* __restrict__ bb,
                const float* __restrict__ f1b, const float* __restrict__ f2b,
                const float* __restrict__ gam,
                float* __restrict__ outp) {
    extern __shared__ char smraw[];
    const uint32_t sbraw = (uint32_t)__cvta_generic_to_shared(smraw);
    const uint32_t sb = (sbraw + 1023u) & ~1023u;
    char* smg = smraw + (sb - sbraw);
    __shared__ int s_id;

    const int bid = blockIdx.x;

#pragma unroll 1
    for (int s = 0; s < 3; ++s) {
        const int start = (s == 0) ? 0 : (s == 1) ? 12 : 15;
        const int nl    = (s == 0) ? 12 : 3;
        const int count = nl * NTILE;

        // ---- segment tile queue ----
#pragma unroll 1
        for (;;) {
            __syncthreads();
            if (threadIdx.x == 0) s_id = atomicAdd(&g_q[s], 1);
            __syncthreads();
            const int idl = s_id;
            if (idl >= count) break;

            const int l   = start + idl / NTILE;
            const int tau = idl % NTILE;
            const int rb  = tau >> 3;
            const int bn  = (tau & 7) * BN;

            const int inS  = l & 1;
            const int outS = (l + 1) & 1;
            const bool last = (l == 17);
            float* dst = layer_dst(l, outp);
            __half* nH = last ? nullptr : g_Ahi + (size_t)outS * NELEM;
            __half* nL = last ? nullptr : g_Alo + (size_t)outS * NELEM;

            if (l > 0) {
                const int th = (l == start) ? 16 : 8;   // 16 = gemm(8)+route(8)
                wait_ge(&g_ready[((l - 1) * NRB + rb) * 8], th);
            }

            gemm_tile(sb, rb * BM, bn,
                      g_Ahi + (size_t)inS * NELEM, g_Alo + (size_t)inS * NELEM,
                      g_Whi + (size_t)l * CDIM * CDIM, g_Wlo + (size_t)l * CDIM * CDIM,
                      bb + (size_t)l * CDIM, dst, nH, nL);
            signal1(&g_ready[(l * NRB + rb) * 8], 1);
        }

        // ---- gating for last layer of segment (11, 14, 17) — all dataflow ----
        const int gl = start + nl - 1;
        const int tt = s;
        const bool last = (gl == 17);
        float* dst = last ? outp : g_bufA;
        __half* nH = last ? nullptr : g_Ahi + (size_t)(((gl + 1) & 1)) * NELEM;
        __half* nL = last ? nullptr : g_Alo + (size_t)(((gl + 1) & 1)) * NELEM;

        if (bid < 3 * BATCH) {
            const int b = bid / 3;
            const int part = bid % 3;
            const int r0 = part * 66;
            const int rcnt = (part == 2) ? 64 : 66;
            const int rlo = (b * HW + r0) >> 7;
            const int rhi = (b * HW + r0 + rcnt - 1) >> 7;
            wait_ge(&g_ready[(gl * NRB + rlo) * 8], 8);
            if (rhi != rlo) wait_ge(&g_ready[(gl * NRB + rhi) * 8], 8);
            pool_part(bid, dst);
            signal1(&g_gc[s * 8], 1);                        // poolc
        }
        if (bid < BATCH) {
            wait_ge(&g_gc[s * 8], 3 * BATCH);
            mlp_phase(smg, bid,
                      g_f1wT + (size_t)tt * HIDN * CDIM, f1b + (size_t)tt * HIDN,
                      g_f2wT + (size_t)tt * AANCH * CDIM * HIDN,
                      f2b + (size_t)tt * AANCH * CDIM,
                      g_gates);
            signal1(&g_gc[(3 + s) * 8], 1);                  // mlpc
        }
        if (bid < NRB) {
            wait_ge(&g_gc[(3 + s) * 8], BATCH);
            route_rb(bid, dst, g_anc0, g_anc1, g_anc2, g_gates, __ldg(&gam[tt]), nH, nL);
            signal1(&g_ready[(gl * NRB + bid) * 8], 8);      // -> 16 unblocks next seg
        }
        // no grid barrier: CTAs flow into the next segment's queue
    }
}

// ---------------------------------------------------------------------------
__global__ void convert_x(const float* __restrict__ x,
                          __half* __restrict__ hi, __half* __restrict__ lo) {
    int i = blockIdx.x * blockDim.x + threadIdx.x;
    if (i >= NELEM / 4) return;
    float4 v = reinterpret_cast<const float4*>(x)[i];
    float l0, l1, l2, l3;
    __half2 h01 = split_hi2(v.x, v.y, l0, l1);
    __half2 h23 = split_hi2(v.z, v.w, l2, l3);
    reinterpret_cast<uint2*>(hi)[i] = make_uint2(*reinterpret_cast<uint32_t*>(&h01),
                                                 *reinterpret_cast<uint32_t*>(&h23));
    reinterpret_cast<uint2*>(lo)[i] = make_uint2(pack_h2(l0, l1), pack_h2(l2, l3));
}

__global__ void convert_w(const float* __restrict__ W,
                          __half* __restrict__ whi, __half* __restrict__ wlo) {
    __shared__ float tile[32][33];
    const int l = blockIdx.z;
    const int kt = blockIdx.y * 32;
    const int nt = blockIdx.x * 32;
    const int tx = threadIdx.x, ty = threadIdx.y;
    const size_t lb = (size_t)l * CDIM * CDIM;
#pragma unroll
    for (int q = 0; q < 4; ++q)
        tile[ty + 8 * q][tx] = W[lb + (size_t)(kt + ty + 8 * q) * CDIM + nt + tx];
    __syncthreads();
#pragma unroll
    for (int q = 0; q < 4; ++q) {
        float v = tile[tx][ty + 8 * q];
        __half h = __float2half_rn(v);
        size_t idx = lb + (size_t)(nt + ty + 8 * q) * CDIM + kt + tx;
        whi[idx] = h;
        wlo[idx] = __float2half_rn(v - __half2float(h));
    }
}

__global__ void convert_r(const float* __restrict__ f1w, const float* __restrict__ f2w,
                          float* __restrict__ f1wT, float* __restrict__ f2wT) {
    const int n1 = AANCH * HIDN * CDIM;
    const int n2 = AANCH * AANCH * CDIM * HIDN;
    for (int i = blockIdx.x * blockDim.x + threadIdx.x; i < n1 + n2;
         i += gridDim.x * blockDim.x) {
        if (i < n1) {
            const int s = i / (HIDN * CDIM);
            const int r = i % (HIDN * CDIM);
            const int h = r / CDIM;
            const int k = r % CDIM;
            f1wT[i] = f1w[(size_t)s * CDIM * HIDN + (size_t)k * HIDN + h];
        } else {
            const int ii = i - n1;
            const int s = ii / (AANCH * CDIM * HIDN);
            const int r = ii % (AANCH * CDIM * HIDN);
            const int j = r / HIDN;
            const int k = r % HIDN;
            f2wT[ii] = f2w[(size_t)s * HIDN * AANCH * CDIM + (size_t)k * AANCH * CDIM + j];
        }
    }
}

// ---------------------------------------------------------------------------
extern "C" void kernel_launch(void* const* d_in, const int* in_sizes, int n_in,
                              void* d_out, int out_size) {
    const float* x   = (const float*)d_in[0];
    const float* bw  = (const float*)d_in[1];
    const float* bb  = (const float*)d_in[2];
    const float* f1w = (const float*)d_in[3];
    const float* f1b = (const float*)d_in[4];
    const float* f2w = (const float*)d_in[5];
    const float* f2b = (const float*)d_in[6];
    const float* gam = (const float*)d_in[7];

    __half *ahi, *alo, *whi, *wlo;
    float *f1wT, *f2wT;
    int *qq, *rdy, *gc;
    cudaGetSymbolAddress((void**)&ahi,  g_Ahi);
    cudaGetSymbolAddress((void**)&alo,  g_Alo);
    cudaGetSymbolAddress((void**)&whi,  g_Whi);
    cudaGetSymbolAddress((void**)&wlo,  g_Wlo);
    cudaGetSymbolAddress((void**)&f1wT, g_f1wT);
    cudaGetSymbolAddress((void**)&f2wT, g_f2wT);
    cudaGetSymbolAddress((void**)&qq,   g_q);
    cudaGetSymbolAddress((void**)&rdy,  g_ready);
    cudaGetSymbolAddress((void**)&gc,   g_gc);

    cudaFuncSetAttribute(stage_mega, cudaFuncAttributeMaxDynamicSharedMemorySize, SMEM_DYN);

    cudaMemsetAsync(qq, 0, 4 * sizeof(int));
    cudaMemsetAsync(rdy, 0, NLAYER * NRB * 8 * sizeof(int));
    cudaMemsetAsync(gc, 0, 6 * 8 * sizeof(int));
    convert_w<<<dim3(CDIM / 32, CDIM / 32, NLAYER), dim3(32, 8)>>>(bw, whi, wlo);
    convert_x<<<(NELEM / 4 + 255) / 256, 256>>>(x, ahi, alo);
    convert_r<<<296, 256>>>(f1w, f2w, f1wT, f2wT);

    stage_mega<<<NCTA, 256, SMEM_DYN>>>(bb, f1b, f2b, gam, (float*)d_out);
}

// round 17
// speedup vs baseline: 1.4260x; 1.4260x over previous
#include <cuda_runtime.h>
#include <cuda_fp16.h>
#include <cstdint>
#include <math.h>

// ---------------------------------------------------------------------------
// Round 17: R15 schedule (best structure: segment queue + gating barriers)
// with 2-product GEMM: activations plain fp16, weights hi/lo split.
// acc = ah*bh + ah*bl  (dropped al*bh = activation rounding, ~1e-4 rel err).
// Tensor work x2/3, A traffic halved, no nLo epilogue.
// ---------------------------------------------------------------------------

#define M_TOT   6272
#define CDIM    512
#define HW      196
#define BATCH   32
#define HIDN    128
#define AANCH   3
#define NELEM   (M_TOT * CDIM)
#define NLAYER  18

#define BM 128
#define BN 64
#define BK 64
#define KSTAGES 8
#define SA_HI 0
#define SB_HI 16384
#define SB_LO 24576
#define STAGE_BYTES 32768
#define SMEM_DYN (1024 + 2 * STAGE_BYTES)

#define NCTA 296
#define NTILE 392
#define NRB  49
#define NGRP 37
#define GRP_STRIDE 32

__device__ float g_bufA[NELEM];
__device__ float g_anc0[NELEM];
__device__ float g_anc1[NELEM];
__device__ float g_anc2[NELEM];
__device__ float g_gates[BATCH * AANCH * CDIM];
__device__ float g_pp[3 * BATCH * CDIM];
__device__ float g_f1wT[AANCH * HIDN * CDIM];
__device__ float g_f2wT[AANCH * AANCH * CDIM * HIDN];
__device__ __half g_Ah[2 * NELEM];
__device__ __half g_Whi[NLAYER * CDIM * CDIM];   // [l][n][k]
__device__ __half g_Wlo[NLAYER * CDIM * CDIM];
__device__ int g_q[4];
__device__ int g_ready[NLAYER * NRB * 8];
__device__ int g_bar[NGRP * GRP_STRIDE + 2 * GRP_STRIDE];
#define ROOT_IDX (NGRP * GRP_STRIDE)
#define GEN_IDX  (NGRP * GRP_STRIDE + GRP_STRIDE)

// ---------------------------------------------------------------------------
__device__ __forceinline__ void grid_sync(int k) {
    __syncthreads();
    if (threadIdx.x == 0) {
        __threadfence();
        const int g = blockIdx.x >> 3;
        int t = atomicAdd(&g_bar[g * GRP_STRIDE], 1);
        if (t == 8 * k + 7) {
            int u = atomicAdd(&g_bar[ROOT_IDX], 1);
            if (u == NGRP * k + (NGRP - 1))
                atomicAdd(&g_bar[GEN_IDX], 1);
        }
        while (__ldcg(&g_bar[GEN_IDX]) <= k) __nanosleep(64);
        __threadfence();
    }
    __syncthreads();
}
__device__ __forceinline__ void wait_ge(const int* p, int v) {
    if (threadIdx.x == 0) {
        while (__ldcg(p) < v) __nanosleep(64);
        __threadfence();
    }
    __syncthreads();
}
__device__ __forceinline__ uint32_t sw128(uint32_t off) {
    return off ^ ((off >> 3) & 0x70);
}
__device__ __forceinline__ void cpa16(uint32_t s, const void* g) {
    asm volatile("cp.async.cg.shared.global [%0], [%1], 16;" :: "r"(s), "l"(g));
}
__device__ __forceinline__ void cpa_commit() {
    asm volatile("cp.async.commit_group;" ::: "memory");
}
__device__ __forceinline__ void cpa_wait1() {
    asm volatile("cp.async.wait_group 1;" ::: "memory");
}
__device__ __forceinline__ void ldsm_x4(uint32_t& r0, uint32_t& r1, uint32_t& r2,
                                        uint32_t& r3, uint32_t a) {
    asm volatile("ldmatrix.sync.aligned.m8n8.x4.shared.b16 {%0,%1,%2,%3}, [%4];"
                 : "=r"(r0), "=r"(r1), "=r"(r2), "=r"(r3) : "r"(a));
}
__device__ __forceinline__ void mma_f16(float* c, const uint32_t* a, const uint32_t* b) {
    asm volatile(
        "mma.sync.aligned.m16n8k16.row.col.f32.f16.f16.f32 "
        "{%0,%1,%2,%3},{%4,%5,%6,%7},{%8,%9},{%0,%1,%2,%3};"
        : "+f"(c[0]), "+f"(c[1]), "+f"(c[2]), "+f"(c[3])
        : "r"(a[0]), "r"(a[1]), "r"(a[2]), "r"(a[3]), "r"(b[0]), "r"(b[1]));
}
__device__ __forceinline__ float gelu_fast(float x) {
    float u = 0.7978845608028654f * fmaf(0.044715f * x, x * x, x);
    float e = __expf(2.0f * u);
    return 0.5f * x * (1.0f + (1.0f - 2.0f / (e + 1.0f)));
}
__device__ __forceinline__ float gelu_tanh(float x) {
    float x3 = x * x * x;
    return 0.5f * x * (1.0f + tanhf(0.7978845608028654f * (x + 0.044715f * x3)));
}
__device__ __forceinline__ uint32_t pack_h2(float a, float b) {
    __half2 t = __floats2half2_rn(a, b);
    return *reinterpret_cast<uint32_t*>(&t);
}

// ---------------------------------------------------------------------------
// One 128x64 output tile, 2-product: acc = ah*bh + ah*bl.
// ---------------------------------------------------------------------------
__device__ void gemm_tile(uint32_t sb, int bm, int bn,
                          const __half* __restrict__ aH,
                          const __half* __restrict__ bHi, const __half* __restrict__ bLo,
                          const float* __restrict__ bias,
                          float* __restrict__ out,
                          __half* __restrict__ nHi) {
    const int t = threadIdx.x;
    const int lane = t & 31;
    const int w = t >> 5;
    const int wm = (w >> 1) * 32;
    const int wn = (w & 1) * 32;

    const int a_row = t >> 3;
    const int a_c16 = t & 7;

    auto load_stage = [&](int s, int buf) {
        const int k0 = s * BK;
        const uint32_t stg = sb + (uint32_t)buf * STAGE_BYTES;
#pragma unroll
        for (int p = 0; p < 4; ++p) {
            const int row = p * 32 + a_row;
            const uint32_t so = sw128((uint32_t)row * 128 + a_c16 * 16);
            const size_t gofs = (size_t)(bm + row) * CDIM + k0 + a_c16 * 8;
            cpa16(stg + SA_HI + so, aH + gofs);
        }
#pragma unroll
        for (int p = 0; p < 2; ++p) {
            const int row = p * 32 + a_row;
            const uint32_t so = sw128((uint32_t)row * 128 + a_c16 * 16);
            const size_t gofs = (size_t)(bn + row) * CDIM + k0 + a_c16 * 8;
            cpa16(stg + SB_HI + so, bHi + gofs);
            cpa16(stg + SB_LO + so, bLo + gofs);
        }
    };

    uint32_t a_off[2];
#pragma unroll
    for (int mi = 0; mi < 2; ++mi)
        a_off[mi] = (uint32_t)(wm + mi * 16 + (lane & 15)) * 128 + ((lane >> 4) & 1) * 16;
    uint32_t b_off[2];
#pragma unroll
    for (int g = 0; g < 2; ++g)
        b_off[g] = (uint32_t)(wn + g * 16 + ((lane >> 4) & 1) * 8 + (lane & 7)) * 128 +
                   ((lane >> 3) & 1) * 16;

    float acc[2][4][4];
#pragma unroll
    for (int mi = 0; mi < 2; ++mi)
#pragma unroll
        for (int nf = 0; nf < 4; ++nf)
#pragma unroll
            for (int r = 0; r < 4; ++r) acc[mi][nf][r] = 0.0f;

    load_stage(0, 0); cpa_commit();
    load_stage(1, 1); cpa_commit();

    uint32_t ah[2][4], bh[2][4], ahn[2][4], bhn[2][4], bl[2][4];

#pragma unroll 1
    for (int s = 0; s < KSTAGES; ++s) {
        cpa_wait1();
        __syncthreads();
        const int buf = s & 1;
        const uint32_t stg = sb + (uint32_t)buf * STAGE_BYTES;

#pragma unroll
        for (int mi = 0; mi < 2; ++mi)
            ldsm_x4(ah[mi][0], ah[mi][1], ah[mi][2], ah[mi][3],
                    stg + SA_HI + sw128(a_off[mi]));
#pragma unroll
        for (int g = 0; g < 2; ++g)
            ldsm_x4(bh[g][0], bh[g][1], bh[g][2], bh[g][3],
                    stg + SB_HI + sw128(b_off[g]));

#pragma unroll
        for (int kk = 0; kk < 4; ++kk) {
            const uint32_t kb = kk * 32;
#pragma unroll
            for (int g = 0; g < 2; ++g)
                ldsm_x4(bl[g][0], bl[g][1], bl[g][2], bl[g][3],
                        stg + SB_LO + sw128(b_off[g] + kb));
            if (kk < 3) {
                const uint32_t kbn = kb + 32;
#pragma unroll
                for (int mi = 0; mi < 2; ++mi)
                    ldsm_x4(ahn[mi][0], ahn[mi][1], ahn[mi][2], ahn[mi][3],
                            stg + SA_HI + sw128(a_off[mi] + kbn));
#pragma unroll
                for (int g = 0; g < 2; ++g)
                    ldsm_x4(bhn[g][0], bhn[g][1], bhn[g][2], bhn[g][3],
                            stg + SB_HI + sw128(b_off[g] + kbn));
            }
#pragma unroll
            for (int mi = 0; mi < 2; ++mi)
#pragma unroll
                for (int nf = 0; nf < 4; ++nf)
                    mma_f16(acc[mi][nf], ah[mi], &bh[nf >> 1][(nf & 1) * 2]);
#pragma unroll
            for (int mi = 0; mi < 2; ++mi)
#pragma unroll
                for (int nf = 0; nf < 4; ++nf)
                    mma_f16(acc[mi][nf], ah[mi], &bl[nf >> 1][(nf & 1) * 2]);
            if (kk < 3) {
#pragma unroll
                for (int mi = 0; mi < 2; ++mi)
#pragma unroll
                    for (int r = 0; r < 4; ++r) ah[mi][r] = ahn[mi][r];
#pragma unroll
                for (int g = 0; g < 2; ++g)
#pragma unroll
                    for (int r = 0; r < 4; ++r) bh[g][r] = bhn[g][r];
            }
        }
        __syncthreads();
        if (s + 2 < KSTAGES) load_stage(s + 2, buf);
        cpa_commit();
    }

    const int r0 = bm + wm + (lane >> 2);
    const int cbase = bn + wn + (lane & 3) * 2;
#pragma unroll
    for (int mi = 0; mi < 2; ++mi) {
#pragma unroll
        for (int nf = 0; nf < 4; ++nf) {
            const int c = cbase + nf * 8;
            const float2 bv = *reinterpret_cast<const float2*>(&bias[c]);
            const int ra = r0 + mi * 16;
            const int rb = ra + 8;
            float v0 = gelu_fast(acc[mi][nf][0] + bv.x);
            float v1 = gelu_fast(acc[mi][nf][1] + bv.y);
            float v2 = gelu_fast(acc[mi][nf][2] + bv.x);
            float v3 = gelu_fast(acc[mi][nf][3] + bv.y);
            if (out) {
                *reinterpret_cast<float2*>(&out[(size_t)ra * CDIM + c]) = make_float2(v0, v1);
                *reinterpret_cast<float2*>(&out[(size_t)rb * CDIM + c]) = make_float2(v2, v3);
            }
            if (nHi) {
                *reinterpret_cast<uint32_t*>(&nHi[(size_t)ra * CDIM + c]) = pack_h2(v0, v1);
                *reinterpret_cast<uint32_t*>(&nHi[(size_t)rb * CDIM + c]) = pack_h2(v2, v3);
            }
        }
    }
}

// ---------------------------------------------------------------------------
__device__ __noinline__ void pool_part(int bid, const float* __restrict__ act) {
    const int b = bid / 3;
    const int part = bid % 3;
    const int r0 = part * 66;
    const int rcnt = (part == 2) ? 64 : 66;
    const int t = threadIdx.x;
    const int c = t * 2;

    const float* p = act + (size_t)(b * HW + r0) * CDIM + c;
    float sx = 0.f, sy = 0.f;
#pragma unroll 4
    for (int r = 0; r < rcnt; ++r) {
        float2 v = __ldcg(reinterpret_cast<const float2*>(p + (size_t)r * CDIM));
        sx += v.x; sy += v.y;
    }
    *reinterpret_cast<float2*>(&g_pp[(size_t)(part * BATCH + b) * CDIM + c]) =
        make_float2(sx, sy);
}

__device__ __noinline__ void mlp_phase(char* sm, int b,
                                       const float* __restrict__ f1wT,
                                       const float* __restrict__ f1b,
                                       const float* __restrict__ f2wT,
                                       const float* __restrict__ f2b,
                                       float* __restrict__ gates) {
    float* ps = (float*)sm;
    float* hs = ps + CDIM;
    float* lg = hs + HIDN;
    const int t = threadIdx.x;

    for (int i = t; i < CDIM; i += 256) {
        float s = __ldcg(&g_pp[(size_t)(0 * BATCH + b) * CDIM + i]) +
                  __ldcg(&g_pp[(size_t)(1 * BATCH + b) * CDIM + i]) +
                  __ldcg(&g_pp[(size_t)(2 * BATCH + b) * CDIM + i]);
        ps[i] = s * (1.0f / (float)HW);
    }
    __syncthreads();

    if (t < HIDN) {
        float acc = f1b[t];
        const float4* wr = reinterpret_cast<const float4*>(f1wT + (size_t)t * CDIM);
#pragma unroll 4
        for (int k4 = 0; k4 < CDIM / 4; ++k4) {
            float4 w = wr[k4];
            acc = fmaf(ps[k4 * 4 + 0], w.x, acc);
            acc = fmaf(ps[k4 * 4 + 1], w.y, acc);
            acc = fmaf(ps[k4 * 4 + 2], w.z, acc);
            acc = fmaf(ps[k4 * 4 + 3], w.w, acc);
        }
        hs[t] = gelu_tanh(acc);
    }
    __syncthreads();

#pragma unroll 1
    for (int j = t; j < AANCH * CDIM; j += 256) {
        float acc = f2b[j];
        const float4* wr = reinterpret_cast<const float4*>(f2wT + (size_t)j * HIDN);
#pragma unroll 8
        for (int k4 = 0; k4 < HIDN / 4; ++k4) {
            float4 w = wr[k4];
            acc = fmaf(hs[k4 * 4 + 0], w.x, acc);
            acc = fmaf(hs[k4 * 4 + 1], w.y, acc);
            acc = fmaf(hs[k4 * 4 + 2], w.z, acc);
            acc = fmaf(hs[k4 * 4 + 3], w.w, acc);
        }
        lg[j] = acc;
    }
    __syncthreads();

    for (int c = t; c < CDIM; c += 256) {
        float l0 = lg[c], l1 = lg[CDIM + c], l2 = lg[2 * CDIM + c];
        float m = fmaxf(l0, fmaxf(l1, l2));
        float e0 = expf(l0 - m), e1 = expf(l1 - m), e2 = expf(l2 - m);
        float inv = 1.0f / (e0 + e1 + e2);
        gates[b * AANCH * CDIM + c]            = e0 * inv;
        gates[b * AANCH * CDIM + CDIM + c]     = e1 * inv;
        gates[b * AANCH * CDIM + 2 * CDIM + c] = e2 * inv;
    }
}

__device__ void route_phase(float* __restrict__ nx,
                            const float* __restrict__ a0, const float* __restrict__ a1,
                            const float* __restrict__ a2, const float* __restrict__ gates,
                            float gamma, __half* __restrict__ nhi) {
    const int per_b = HW * CDIM / 4;
    for (int i = blockIdx.x * 256 + threadIdx.x; i < NELEM / 4; i += NCTA * 256) {
        const int b = i / per_b;
        const int c4 = i & (CDIM / 4 - 1);
        const float4 g0 = __ldcg(reinterpret_cast<const float4*>(&gates[b * AANCH * CDIM + c4 * 4]));
        const float4 g1 = __ldcg(reinterpret_cast<const float4*>(&gates[b * AANCH * CDIM + CDIM + c4 * 4]));
        const float4 g2 = __ldcg(reinterpret_cast<const float4*>(&gates[b * AANCH * CDIM + 2 * CDIM + c4 * 4]));

        float4 v  = __ldcg(reinterpret_cast<const float4*>(nx) + i);
        float4 x0 = __ldcg(reinterpret_cast<const float4*>(a0) + i);
        float4 x1 = __ldcg(reinterpret_cast<const float4*>(a1) + i);
        float4 x2 = __ldcg(reinterpret_cast<const float4*>(a2) + i);

        v.x += gamma * (g0.x * x0.x + g1.x * x1.x + g2.x * x2.x);
        v.y += gamma * (g0.y * x0.y + g1.y * x1.y + g2.y * x2.y);
        v.z += gamma * (g0.z * x0.z + g1.z * x1.z + g2.z * x2.z);
        v.w += gamma * (g0.w * x0.w + g1.w * x1.w + g2.w * x2.w);

        reinterpret_cast<float4*>(nx)[i] = v;

        if (nhi) {
            reinterpret_cast<uint2*>(nhi)[i] =
                make_uint2(pack_h2(v.x, v.y), pack_h2(v.z, v.w));
        }
    }
}

__device__ __forceinline__ float* layer_dst(int l, float* outp) {
    if (l == 1)  return g_anc0;
    if (l == 4)  return g_anc1;
    if (l == 9)  return g_anc2;
    if (l == 17) return outp;
    if (l == 11 || l == 14) return g_bufA;
    return nullptr;
}

// ---------------------------------------------------------------------------
__global__ __launch_bounds__(256, 2)
void stage_mega(const float* __restrict__ bb,
                const float* __restrict__ f1b, const float* __restrict__ f2b,
                const float* __restrict__ gam,
                float* __restrict__ outp) {
    extern __shared__ char smraw[];
    const uint32_t sbraw = (uint32_t)__cvta_generic_to_shared(smraw);
    const uint32_t sb = (sbraw + 1023u) & ~1023u;
    char* smg = smraw + (sb - sbraw);
    __shared__ int s_id;

    const int bid = blockIdx.x;
    int bk = 0;

#pragma unroll 1
    for (int s = 0; s < 3; ++s) {
        const int start = (s == 0) ? 0 : (s == 1) ? 12 : 15;
        const int nl    = (s == 0) ? 12 : 3;
        const int count = nl * NTILE;

        // ---- segment tile queue ----
#pragma unroll 1
        for (;;) {
            __syncthreads();
            if (threadIdx.x == 0) s_id = atomicAdd(&g_q[s], 1);
            __syncthreads();
            const int idl = s_id;
            if (idl >= count) break;

            const int l   = start + idl / NTILE;
            const int tau = idl % NTILE;
            const int rb  = tau >> 3;
            const int bn  = (tau & 7) * BN;

            const int inS  = l & 1;
            const int outS = (l + 1) & 1;
            const bool last = (l == 17);
            float* dst = layer_dst(l, outp);
            __half* nH = last ? nullptr : g_Ah + (size_t)outS * NELEM;

            if (l != start)
                wait_ge(&g_ready[((l - 1) * NRB + rb) * 8], 8);

            gemm_tile(sb, rb * BM, bn,
                      g_Ah + (size_t)inS * NELEM,
                      g_Whi + (size_t)l * CDIM * CDIM, g_Wlo + (size_t)l * CDIM * CDIM,
                      bb + (size_t)l * CDIM, dst, nH);
            __syncthreads();
            if (threadIdx.x == 0) {
                __threadfence();
                atomicAdd(&g_ready[(l * NRB + rb) * 8], 1);
            }
        }
        grid_sync(bk++);

        // ---- gating for last layer of segment (11, 14, 17) ----
        const int gl = start + nl - 1;
        const int tt = s;
        const bool last = (gl == 17);
        float* dst = last ? outp : g_bufA;
        __half* nH = last ? nullptr : g_Ah + (size_t)(((gl + 1) & 1)) * NELEM;

        if (bid < 3 * BATCH)
            pool_part(bid, dst);
        grid_sync(bk++);
        if (bid < BATCH)
            mlp_phase(smg, bid,
                      g_f1wT + (size_t)tt * HIDN * CDIM, f1b + (size_t)tt * HIDN,
                      g_f2wT + (size_t)tt * AANCH * CDIM * HIDN,
                      f2b + (size_t)tt * AANCH * CDIM,
                      g_gates);
        grid_sync(bk++);
        route_phase(dst, g_anc0, g_anc1, g_anc2, g_gates, __ldg(&gam[tt]), nH);
        grid_sync(bk++);
    }
}

// ---------------------------------------------------------------------------
__global__ void convert_x(const float* __restrict__ x, __half* __restrict__ hi) {
    int i = blockIdx.x * blockDim.x + threadIdx.x;
    if (i >= NELEM / 4) return;
    float4 v = reinterpret_cast<const float4*>(x)[i];
    reinterpret_cast<uint2*>(hi)[i] = make_uint2(pack_h2(v.x, v.y), pack_h2(v.z, v.w));
}

__global__ void convert_w(const float* __restrict__ W,
                          __half* __restrict__ whi, __half* __restrict__ wlo) {
    __shared__ float tile[32][33];
    const int l = blockIdx.z;
    const int kt = blockIdx.y * 32;
    const int nt = blockIdx.x * 32;
    const int tx = threadIdx.x, ty = threadIdx.y;
    const size_t lb = (size_t)l * CDIM * CDIM;
#pragma unroll
    for (int q = 0; q < 4; ++q)
        tile[ty + 8 * q][tx] = W[lb + (size_t)(kt + ty + 8 * q) * CDIM + nt + tx];
    __syncthreads();
#pragma unroll
    for (int q = 0; q < 4; ++q) {
        float v = tile[tx][ty + 8 * q];
        __half h = __float2half_rn(v);
        size_t idx = lb + (size_t)(nt + ty + 8 * q) * CDIM + kt + tx;
        whi[idx] = h;
        wlo[idx] = __float2half_rn(v - __half2float(h));
    }
}

__global__ void convert_r(const float* __restrict__ f1w, const float* __restrict__ f2w,
                          float* __restrict__ f1wT, float* __restrict__ f2wT) {
    const int n1 = AANCH * HIDN * CDIM;
    const int n2 = AANCH * AANCH * CDIM * HIDN;
    for (int i = blockIdx.x * blockDim.x + threadIdx.x; i < n1 + n2;
         i += gridDim.x * blockDim.x) {
        if (i < n1) {
            const int s = i / (HIDN * CDIM);
            const int r = i % (HIDN * CDIM);
            const int h = r / CDIM;
            const int k = r % CDIM;
            f1wT[i] = f1w[(size_t)s * CDIM * HIDN + (size_t)k * HIDN + h];
        } else {
            const int ii = i - n1;
            const int s = ii / (AANCH * CDIM * HIDN);
            const int r = ii % (AANCH * CDIM * HIDN);
            const int j = r / HIDN;
            const int k = r % HIDN;
            f2wT[ii] = f2w[(size_t)s * HIDN * AANCH * CDIM + (size_t)k * AANCH * CDIM + j];
        }
    }
}

// ---------------------------------------------------------------------------
extern "C" void kernel_launch(void* const* d_in, const int* in_sizes, int n_in,
                              void* d_out, int out_size) {
    const float* x   = (const float*)d_in[0];
    const float* bw  = (const float*)d_in[1];
    const float* bb  = (const float*)d_in[2];
    const float* f1w = (const float*)d_in[3];
    const float* f1b = (const float*)d_in[4];
    const float* f2w = (const float*)d_in[5];
    const float* f2b = (const float*)d_in[6];
    const float* gam = (const float*)d_in[7];

    __half *ah, *whi, *wlo;
    float *f1wT, *f2wT;
    int *bar, *qq, *rdy;
    cudaGetSymbolAddress((void**)&ah,   g_Ah);
    cudaGetSymbolAddress((void**)&whi,  g_Whi);
    cudaGetSymbolAddress((void**)&wlo,  g_Wlo);
    cudaGetSymbolAddress((void**)&f1wT, g_f1wT);
    cudaGetSymbolAddress((void**)&f2wT, g_f2wT);
    cudaGetSymbolAddress((void**)&bar,  g_bar);
    cudaGetSymbolAddress((void**)&qq,   g_q);
    cudaGetSymbolAddress((void**)&rdy,  g_ready);

    cudaFuncSetAttribute(stage_mega, cudaFuncAttributeMaxDynamicSharedMemorySize, SMEM_DYN);

    cudaMemsetAsync(bar, 0, (NGRP * GRP_STRIDE + 2 * GRP_STRIDE) * sizeof(int));
    cudaMemsetAsync(qq, 0, 4 * sizeof(int));
    cudaMemsetAsync(rdy, 0, NLAYER * NRB * 8 * sizeof(int));
    convert_w<<<dim3(CDIM / 32, CDIM / 32, NLAYER), dim3(32, 8)>>>(bw, whi, wlo);
    convert_x<<<(NELEM / 4 + 255) / 256, 256>>>(x, ah);
    convert_r<<<296, 256>>>(f1w, f2w, f1wT, f2wT);

    stage_mega<<<NCTA, 256, SMEM_DYN>>>(bb, f1b, f2b, gam, (float*)d_out);
}